// round 17
// baseline (speedup 1.0000x reference)
#include <cuda_runtime.h>
#include <math.h>

// ---------------------------------------------------------------------------
// GRAPEIso: folded 96-output 3x3 conv + gaussian splatting.
// R17: (1) fold reverted to R4 warp-per-output (measured-fastest, 5.6us);
// (2) raster processes gaussian PAIRS (gx, gx+1) per thread: overlapping
// 4x4 footprints are merged so shared pixels get ONE 3-atomic update with
// the fused contribution a0*rgb0 + a1*rgb1 (~30% fewer smem atomics, the
// measured raster bottleneck), and the candidate loop halves (242 pairs,
// single pass). Predict frozen (R16: T=2 f32x2). PDL throughout.
// ---------------------------------------------------------------------------

#define BATCH   4
#define INH     128
#define INW     128
#define GH      256
#define GW      256
#define IMH     256
#define IMW     256
#define NGAUSS  (GH * GW)

#define TW      16
#define TH      16

typedef unsigned long long ull;

#define FMA_F32X2(acc, a, b) \
    asm("fma.rn.f32x2 %0, %1, %2, %0;" : "+l"(acc) : "l"(a), "l"(b))
#define PACK_F32X2(out, lo, hi) \
    asm("mov.b64 %0, {%1, %2};" : "=l"(out) : "f"(lo), "f"(hi))
#define UNPACK_F32X2(lo, hi, in) \
    asm("mov.b64 {%0, %1}, %2;" : "=f"(lo), "=f"(hi) : "l"(in))

__device__ __forceinline__ float tanh_approx(float x) {
    float r;
    asm("tanh.approx.f32 %0, %1;" : "=f"(r) : "f"(x));
    return r;
}

// Register-resident 4-way select (compiles to SEL chain; avoids local mem)
__device__ __forceinline__ float sel4(float e0, float e1, float e2, float e3,
                                      int k) {
    float r = e0;
    r = (k == 1) ? e1 : r;
    r = (k == 2) ? e2 : r;
    r = (k == 3) ? e3 : r;
    return ((unsigned)k < 4u) ? r : 0.f;
}

// Scratch (allocation-free contract: __device__ globals)
__device__ float  g_weff[4 * 27 * 24];          // [uv][t][o], o contiguous
__device__ float  g_beff[4 * 24];               // [uv][o]
__device__ float2 g_center[BATCH * NGAUSS];     // (cx, cy)
__device__ float4 g_color [BATCH * NGAUSS];     // (r, g, b, pad)

// ---------------------------------------------------------------------------
// Kernel 0: weight fold - R4 warp-per-output version (measured fastest:
// 5.6us vs 6.4-7.2 for all CTA-cooperative variants).
// ---------------------------------------------------------------------------
__global__ void __launch_bounds__(128) fold_kernel(
    const float* __restrict__ w_enc,   // (1024, 3, 3, 3) -> [C*27 + t]
    const float* __restrict__ b_enc,   // (1024,)
    const float* __restrict__ w_head,  // (24, 256)
    const float* __restrict__ b_head)  // (24,)
{
    int w    = blockIdx.x * 4 + (threadIdx.x >> 5);
    int lane = threadIdx.x & 31;

    if (w < 2592) {
        int uv = w / 648;
        int r  = w - uv * 648;
        int t  = r / 24;
        int o  = r - t * 24;
        int u = uv >> 1, v = uv & 1;

        float acc = 0.f;
        #pragma unroll
        for (int k = 0; k < 8; k++) {
            int ch = k * 32 + lane;
            int c = ch >> 2, a = (ch >> 1) & 1, e = ch & 1;
            int C = c * 16 + (2 * u + a) * 4 + (2 * v + e);
            acc = fmaf(__ldg(w_head + o * 256 + ch), __ldg(w_enc + C * 27 + t), acc);
        }
        #pragma unroll
        for (int s = 16; s; s >>= 1) acc += __shfl_xor_sync(~0u, acc, s);
        if (lane == 0) g_weff[uv * 648 + t * 24 + o] = acc;
    } else if (w < 2688) {
        int idx = w - 2592;
        int uv  = idx / 24;
        int o   = idx - uv * 24;
        int u = uv >> 1, v = uv & 1;

        float acc = 0.f;
        #pragma unroll
        for (int k = 0; k < 8; k++) {
            int ch = k * 32 + lane;
            int c = ch >> 2, a = (ch >> 1) & 1, e = ch & 1;
            int C = c * 16 + (2 * u + a) * 4 + (2 * v + e);
            acc = fmaf(__ldg(w_head + o * 256 + ch), __ldg(b_enc + C), acc);
        }
        #pragma unroll
        for (int s = 16; s; s >>= 1) acc += __shfl_xor_sync(~0u, acc, s);
        if (lane == 0) g_beff[uv * 24 + o] = b_head[o] + acc;
    }
}

// ---------------------------------------------------------------------------
// Predict epilogue: softmax/tanh combine + store one gaussian record.
// ---------------------------------------------------------------------------
__device__ __forceinline__ void emit_gauss(const float* acc, int i, int j,
                                           int uv, int b)
{
    float lg0 = acc[5], lg1 = acc[11], lg2 = acc[17], lg3 = acc[23];
    float m = fmaxf(fmaxf(lg0, lg1), fmaxf(lg2, lg3));
    float w0 = __expf(lg0 - m), w1 = __expf(lg1 - m);
    float w2 = __expf(lg2 - m), w3 = __expf(lg3 - m);
    float inv = 1.f / (w0 + w1 + w2 + w3);

    float r = 0.f, g = 0.f, bl = 0.f, ox = 0.f, oy = 0.f;
    #pragma unroll
    for (int k = 0; k < 4; k++) {
        float wk = ((k == 0) ? w0 : (k == 1) ? w1 : (k == 2) ? w2 : w3) * inv;
        r  = fmaf(acc[k * 6 + 0], wk, r);
        g  = fmaf(acc[k * 6 + 1], wk, g);
        bl = fmaf(acc[k * 6 + 2], wk, bl);
        ox = fmaf(tanh_approx(acc[k * 6 + 3]), wk, ox);
        oy = fmaf(tanh_approx(acc[k * 6 + 4]), wk, oy);
    }

    int u = uv >> 1, v = uv & 1;
    int gy = 2 * i + u, gx = 2 * j + v;
    float cx = (float)gx + 2.f * ox - 1.f;
    float cy = (float)gy + 2.f * oy - 1.f;

    int gidx = b * NGAUSS + gy * GW + gx;
    g_center[gidx] = make_float2(cx, cy);
    g_color[gidx]  = make_float4(r, g, bl, 0.f);
}

// ---------------------------------------------------------------------------
// Kernel 1: predict (frozen R16). 512 CTAs x 64 threads; thread = two
// horizontally adjacent pixels sharing each weight LDS.128; f32x2 FFMA.
// ---------------------------------------------------------------------------
__global__ void __launch_bounds__(64) predict_kernel(const float* __restrict__ inp)
{
    __shared__ __align__(16) float sW[4 * 648];      // [uv][t][o]
    __shared__ __align__(16) float sB[4 * 24];

    int idx = blockIdx.x * 64 + threadIdx.x;    // 0..32767 pixel-pairs
    int b   = idx >> 13;
    int rem = idx & 8191;
    int i   = rem >> 6;
    int j   = (rem & 63) * 2;

    ull patch2[36];
    const float* ib = inp + (size_t)b * 3 * INH * INW;
    #pragma unroll
    for (int ic = 0; ic < 3; ic++) {
        #pragma unroll
        for (int ky = 0; ky < 3; ky++) {
            int y = i + ky - 1;
            #pragma unroll
            for (int kx = 0; kx < 4; kx++) {
                int x = j + kx - 1;
                float vv = 0.f;
                if ((unsigned)y < INH && (unsigned)x < INW)
                    vv = __ldg(ib + ic * INH * INW + y * INW + x);
                PACK_F32X2(patch2[(ic * 3 + ky) * 4 + kx], vv, vv);
            }
        }
    }

    cudaGridDependencySynchronize();

    for (int t = threadIdx.x; t < 4 * 648; t += 64) sW[t] = g_weff[t];
    for (int t = threadIdx.x; t < 96; t += 64) sB[t] = g_beff[t];
    __syncthreads();

    #pragma unroll
    for (int uv = 0; uv < 4; uv++) {
        ull accA[12], accB[12];
        const ull* sB2 = (const ull*)(sB + uv * 24);
        #pragma unroll
        for (int q = 0; q < 12; q++) { accA[q] = sB2[q]; accB[q] = sB2[q]; }

        const ulonglong2* wrow = (const ulonglong2*)(sW + uv * 648);
        #pragma unroll
        for (int t = 0; t < 27; t++) {
            int ic = t / 9, r9 = t - ic * 9;
            int ky = r9 / 3, kx = r9 - ky * 3;
            ull xa = patch2[(ic * 3 + ky) * 4 + kx];
            ull xb = patch2[(ic * 3 + ky) * 4 + kx + 1];
            #pragma unroll
            for (int q = 0; q < 6; q++) {
                ulonglong2 w2 = wrow[t * 6 + q];
                FMA_F32X2(accA[2 * q],     w2.x, xa);
                FMA_F32X2(accA[2 * q + 1], w2.y, xa);
                FMA_F32X2(accB[2 * q],     w2.x, xb);
                FMA_F32X2(accB[2 * q + 1], w2.y, xb);
            }
        }

        float fa[24], fb[24];
        #pragma unroll
        for (int q = 0; q < 12; q++) {
            UNPACK_F32X2(fa[2 * q], fa[2 * q + 1], accA[q]);
            UNPACK_F32X2(fb[2 * q], fb[2 * q + 1], accB[q]);
        }
        emit_gauss(fa, i, j,     uv, b);
        emit_gauss(fb, i, j + 1, uv, b);
    }
}

// ---------------------------------------------------------------------------
// Kernel 2: rasterize with gaussian-pair merging. CTA = 16x16 tile; halo
// candidates processed as 242 (gx, gx+1) pairs (single loop pass, 256 thr).
// Overlapping pixels of the pair get ONE fused atomic triple. Per-gaussian
// alpha threshold preserved exactly. Interleaved acc[3p+ch]; jp*3 mod 11
// permutation keeps lanes' unions apart; PDL preamble.
// ---------------------------------------------------------------------------
__global__ void __launch_bounds__(256) raster_kernel(float* __restrict__ out)
{
    __shared__ float acc[3 * TH * TW];  // interleaved [p][ch]

    int tx0 = (blockIdx.x & 15) * TW;
    int ty0 = (blockIdx.x >> 4) * TH;
    int b   = blockIdx.y;

    for (int p = threadIdx.x; p < 3 * TH * TW; p += 256) acc[p] = 0.f;

    cudaGridDependencySynchronize();
    __syncthreads();

    const float2* ctr = g_center + b * NGAUSS;
    const float4* col = g_color  + b * NGAUSS;

    for (int idx = threadIdx.x; idx < 22 * 11; idx += 256) {
        int ry = idx / 11;
        int jp = idx - ry * 11;
        jp = (jp * 3) % 11;                 // de-conflict permutation
        int gy  = ty0 - 2 + ry;
        int gx0 = tx0 - 2 + jp * 2;
        if ((unsigned)gy >= GH) continue;

        int gbase = gy * GW;
        bool v0 = (unsigned)gx0 < GW;
        bool v1 = (unsigned)(gx0 + 1) < GW;

        float2 c0 = v0 ? ctr[gbase + gx0]     : make_float2(-1e9f, -1e9f);
        float2 c1 = v1 ? ctr[gbase + gx0 + 1] : make_float2(-1e9f, -1e9f);

        float ix0f = floorf(c0.x), iy0f = floorf(c0.y);
        float ix1f = floorf(c1.x), iy1f = floorf(c1.y);
        int ix0 = (int)ix0f, iy0 = (int)iy0f;
        int ix1 = (int)ix1f, iy1 = (int)iy1f;

        // footprint [i-1, i+2] intersects tile?
        bool a0 = v0 && (ix0 <= tx0 + TW) && (ix0 >= tx0 - 2) &&
                        (iy0 <= ty0 + TH) && (iy0 >= ty0 - 2);
        bool a1 = v1 && (ix1 <= tx0 + TW) && (ix1 >= tx0 - 2) &&
                        (iy1 <= ty0 + TH) && (iy1 >= ty0 - 2);
        if (!a0 && !a1) continue;

        float4 col0 = a0 ? col[gbase + gx0]     : make_float4(0.f, 0.f, 0.f, 0.f);
        float4 col1 = a1 ? col[gbase + gx0 + 1] : make_float4(0.f, 0.f, 0.f, 0.f);

        float ex00 = 0.f, ex01 = 0.f, ex02 = 0.f, ex03 = 0.f;
        float ey00 = 0.f, ey01 = 0.f, ey02 = 0.f, ey03 = 0.f;
        float ex10 = 0.f, ex11 = 0.f, ex12 = 0.f, ex13 = 0.f;
        float ey10 = 0.f, ey11 = 0.f, ey12 = 0.f, ey13 = 0.f;
        if (a0) {
            float fx = c0.x - ix0f, fy = c0.y - iy0f;
            ex00 = __expf(-2.f * (fx + 1.f) * (fx + 1.f));
            ex01 = __expf(-2.f * fx * fx);
            ex02 = __expf(-2.f * (1.f - fx) * (1.f - fx));
            ex03 = __expf(-2.f * (2.f - fx) * (2.f - fx));
            ey00 = __expf(-2.f * (fy + 1.f) * (fy + 1.f));
            ey01 = __expf(-2.f * fy * fy);
            ey02 = __expf(-2.f * (1.f - fy) * (1.f - fy));
            ey03 = __expf(-2.f * (2.f - fy) * (2.f - fy));
        }
        if (a1) {
            float fx = c1.x - ix1f, fy = c1.y - iy1f;
            ex10 = __expf(-2.f * (fx + 1.f) * (fx + 1.f));
            ex11 = __expf(-2.f * fx * fx);
            ex12 = __expf(-2.f * (1.f - fx) * (1.f - fx));
            ex13 = __expf(-2.f * (2.f - fx) * (2.f - fx));
            ey10 = __expf(-2.f * (fy + 1.f) * (fy + 1.f));
            ey11 = __expf(-2.f * fy * fy);
            ey12 = __expf(-2.f * (1.f - fy) * (1.f - fy));
            ey13 = __expf(-2.f * (2.f - fy) * (2.f - fy));
        }

        // Union bbox (alive-guarded)
        int ixA = a0 ? ix0 : ix1, ixB = a1 ? ix1 : ix0;
        int iyA = a0 ? iy0 : iy1, iyB = a1 ? iy1 : iy0;
        int ixlo = min(ixA, ixB), ixhi = max(ixA, ixB);
        int iylo = min(iyA, iyB), iyhi = max(iyA, iyB);
        int nrow = iyhi - iylo + 4;
        int ncol = ixhi - ixlo + 4;

        for (int rr = 0; rr < nrow; rr++) {
            int py = iylo - 1 + rr;
            int ty = py - ty0;
            if ((unsigned)ty >= TH) continue;
            float ey0v = sel4(ey00, ey01, ey02, ey03, py - iy0 + 1);
            float ey1v = sel4(ey10, ey11, ey12, ey13, py - iy1 + 1);
            for (int cc = 0; cc < ncol; cc++) {
                int px = ixlo - 1 + cc;
                int tx = px - tx0;
                if ((unsigned)tx >= TW) continue;
                float av0 = sel4(ex00, ex01, ex02, ex03, px - ix0 + 1) * ey0v;
                float av1 = sel4(ex10, ex11, ex12, ex13, px - ix1 + 1) * ey1v;
                av0 = fminf(av0, 0.999f);
                av1 = fminf(av1, 0.999f);
                av0 = (av0 > (1.0f / 255.0f)) ? av0 : 0.f;
                av1 = (av1 > (1.0f / 255.0f)) ? av1 : 0.f;
                if (av0 + av1 > 0.f) {
                    int p3 = (ty * TW + tx) * 3;
                    atomicAdd(&acc[p3 + 0], fmaf(av0, col0.x, av1 * col1.x));
                    atomicAdd(&acc[p3 + 1], fmaf(av0, col0.y, av1 * col1.y));
                    atomicAdd(&acc[p3 + 2], fmaf(av0, col0.z, av1 * col1.z));
                }
            }
        }
    }
    __syncthreads();

    float* ob = out + (size_t)b * 3 * IMH * IMW;
    for (int p = threadIdx.x; p < TH * TW; p += 256) {
        int ty = p >> 4;
        int tx = p & 15;
        int o  = (ty0 + ty) * IMW + (tx0 + tx);
        #pragma unroll
        for (int ch = 0; ch < 3; ch++) {
            float vv = acc[p * 3 + ch];
            ob[ch * IMH * IMW + o] = fminf(fmaxf(vv, 0.f), 1.f);
        }
    }
}

// ---------------------------------------------------------------------------
// Launch: fold -> predict -> raster, one stream, PDL on the two successors.
// No streams/events/allocations. Inputs: inp, w_enc, b_enc, w_head, b_head.
// ---------------------------------------------------------------------------
extern "C" void kernel_launch(void* const* d_in, const int* in_sizes, int n_in,
                              void* d_out, int out_size)
{
    const float* inp    = (const float*)d_in[0];
    const float* w_enc  = (const float*)d_in[1];
    const float* b_enc  = (const float*)d_in[2];
    const float* w_head = (const float*)d_in[3];
    const float* b_head = (const float*)d_in[4];
    float* out = (float*)d_out;

    fold_kernel<<<672, 128>>>(w_enc, b_enc, w_head, b_head);

    cudaLaunchAttribute pdl[1];
    pdl[0].id = cudaLaunchAttributeProgrammaticStreamSerialization;
    pdl[0].val.programmaticStreamSerializationAllowed = 1;

    {
        cudaLaunchConfig_t cfg = {};
        cfg.gridDim  = dim3(512);
        cfg.blockDim = dim3(64);
        cfg.attrs    = pdl;
        cfg.numAttrs = 1;
        if (cudaLaunchKernelEx(&cfg, predict_kernel, inp) != cudaSuccess)
            predict_kernel<<<512, 64>>>(inp);
    }
    {
        cudaLaunchConfig_t cfg = {};
        cfg.gridDim  = dim3(256, BATCH);
        cfg.blockDim = dim3(256);
        cfg.attrs    = pdl;
        cfg.numAttrs = 1;
        if (cudaLaunchKernelEx(&cfg, raster_kernel, out) != cudaSuccess)
            raster_kernel<<<dim3(256, BATCH), 256>>>(out);
    }
}